// round 1
// baseline (speedup 1.0000x reference)
#include <cuda_runtime.h>
#include <cuda_bf16.h>

// Problem constants
#define BATCH 2
#define LEN   256
#define DMODEL 64
#define NHEADS 4
#define DHEAD 16
#define NROWS (BATCH*LEN*LEN)          // 131072

// Scratch (allocation-free rule: __device__ globals)
__device__ float g_Q[NROWS*DMODEL];
__device__ float g_K[NROWS*DMODEL];
__device__ float g_V[NROWS*DMODEL];
__device__ float g_G[NROWS*DMODEL];    // gate in, gated attention output (in-place)

typedef unsigned long long u64;

__device__ __forceinline__ u64 pk2(float lo, float hi) {
    u64 r; asm("mov.b64 %0, {%1,%2};" : "=l"(r) : "f"(lo), "f"(hi)); return r;
}
__device__ __forceinline__ void up2(u64 v, float& lo, float& hi) {
    asm("mov.b64 {%0,%1}, %2;" : "=f"(lo), "=f"(hi) : "l"(v));
}
__device__ __forceinline__ u64 ffma2(u64 a, u64 b, u64 c) {
    u64 d; asm("fma.rn.f32x2 %0, %1, %2, %3;" : "=l"(d) : "l"(a), "l"(b), "l"(c)); return d;
}

// ---------------------------------------------------------------------------
// Kernel 1: LayerNorm + Q/K/V/Gate projections.
// Block: 256 threads, 16 rows. SMEM: combined weights transposed [i][o0..255]
// (o<64:Q, <128:K, <192:V, <256:G), pad 257 for conflict-free access.
// Thread t: out-channel c = t&63, column groups g*64+c, rows r0..r0+3.
// ---------------------------------------------------------------------------
#define K1_ROWS 16
#define K1_WPAD 257
#define K1_SMEM ((64*K1_WPAD + K1_ROWS*64)*4)

__global__ void __launch_bounds__(256) k_ln_proj(
    const float* __restrict__ z, const float* __restrict__ ln_scale,
    const float* __restrict__ ln_bias,
    const float* __restrict__ Wq, const float* __restrict__ Wk,
    const float* __restrict__ Wv, const float* __restrict__ Wg,
    const float* __restrict__ bg)
{
    extern __shared__ float sm1[];
    float* sW   = sm1;                 // [64][257]  sW[i*257+o]
    float* s_zn = sm1 + 64*K1_WPAD;    // [16][64]

    const int tid  = threadIdx.x;
    const int row0 = blockIdx.x * K1_ROWS;

    // Stage weights transposed: global read coalesced, smem store conflict-free
    const float* Ws[4] = {Wq, Wk, Wv, Wg};
    #pragma unroll
    for (int m = 0; m < 4; m++) {
        const float* W = Ws[m];
        #pragma unroll
        for (int idx = tid; idx < 64*64; idx += 256) {
            int o = idx >> 6, i = idx & 63;
            sW[i*K1_WPAD + m*64 + o] = W[idx];
        }
    }

    // LayerNorm: warp w handles rows 2w, 2w+1
    {
        const int w = tid >> 5, lane = tid & 31;
        #pragma unroll
        for (int rr = 0; rr < 2; rr++) {
            const int r = 2*w + rr;
            const float* zr = z + (size_t)(row0 + r) * 64;
            float a = zr[lane], b = zr[lane + 32];
            float s = a + b, ss = a*a + b*b;
            #pragma unroll
            for (int off = 16; off; off >>= 1) {
                s  += __shfl_xor_sync(0xffffffffu, s,  off);
                ss += __shfl_xor_sync(0xffffffffu, ss, off);
            }
            float mu  = s * (1.0f/64.0f);
            float var = ss * (1.0f/64.0f) - mu*mu;
            float rs  = rsqrtf(var + 1e-5f);
            s_zn[r*64 + lane]      = (a - mu) * rs * ln_scale[lane]      + ln_bias[lane];
            s_zn[r*64 + lane + 32] = (b - mu) * rs * ln_scale[lane + 32] + ln_bias[lane + 32];
        }
    }
    __syncthreads();

    const int c  = tid & 63;
    const int r0 = (tid >> 6) * 4;
    float acc[4][4] = {};   // [g][r]
    #pragma unroll 4
    for (int i = 0; i < 64; i++) {
        float z0 = s_zn[(r0+0)*64 + i];
        float z1 = s_zn[(r0+1)*64 + i];
        float z2 = s_zn[(r0+2)*64 + i];
        float z3 = s_zn[(r0+3)*64 + i];
        #pragma unroll
        for (int g = 0; g < 4; g++) {
            float w = sW[i*K1_WPAD + g*64 + c];
            acc[g][0] += z0*w; acc[g][1] += z1*w;
            acc[g][2] += z2*w; acc[g][3] += z3*w;
        }
    }
    const float bgc = bg[c];
    #pragma unroll
    for (int r = 0; r < 4; r++) {
        const size_t gi = (size_t)(row0 + r0 + r) * 64 + c;
        g_Q[gi] = acc[0][r];
        g_K[gi] = acc[1][r];
        g_V[gi] = acc[2][r];
        g_G[gi] = 1.0f / (1.0f + __expf(-(acc[3][r] + bgc)));
    }
}

// ---------------------------------------------------------------------------
// Kernel 2: row-wise attention, all 4 heads per (b,l) block.
// Block: 512 threads = 4 heads x 128 threads; each thread owns 2 query rows.
// K,V tiles (256x64 fp32 each) in SMEM. 2-pass softmax.
// Hot loops use fma.rn.f32x2 packed FMA with LDS.64 K/V pair loads.
// Gate applied in epilogue; gated output written back into g_G.
// ---------------------------------------------------------------------------
#define K2_SMEM (2*256*64*4)

__global__ void __launch_bounds__(512) k_attn()
{
    extern __shared__ float sm2[];
    float* sK = sm2;
    float* sV = sm2 + 256*64;

    const int tid  = threadIdx.x;
    const int base = blockIdx.x * 256;     // blockIdx.x = b*L + l

    {
        const float4* K4 = (const float4*)(g_K + (size_t)base * 64);
        const float4* V4 = (const float4*)(g_V + (size_t)base * 64);
        float4* sK4 = (float4*)sK; float4* sV4 = (float4*)sV;
        #pragma unroll
        for (int idx = tid; idx < 256*16; idx += 512) {
            sK4[idx] = K4[idx];
            sV4[idx] = V4[idx];
        }
    }
    __syncthreads();

    const int h = tid >> 7;         // head 0..3 (whole warp same head)
    const int t = tid & 127;
    const int i0 = t, i1 = t + 128;

    // Q rows (x softmax scale 1/sqrt(16)=0.25), packed as f32 pairs
    u64 q0[8], q1[8];
    {
        const float4* Q0 = (const float4*)(g_Q + (size_t)(base + i0)*64 + h*16);
        const float4* Q1 = (const float4*)(g_Q + (size_t)(base + i1)*64 + h*16);
        #pragma unroll
        for (int m = 0; m < 4; m++) {
            float4 a = Q0[m], b = Q1[m];
            q0[2*m]   = pk2(a.x*0.25f, a.y*0.25f);
            q0[2*m+1] = pk2(a.z*0.25f, a.w*0.25f);
            q1[2*m]   = pk2(b.x*0.25f, b.y*0.25f);
            q1[2*m+1] = pk2(b.z*0.25f, b.w*0.25f);
        }
    }

    const u64* Kp = (const u64*)sK;   // row j -> j*32 pairs; head offset h*8
    const u64* Vp = (const u64*)sV;
    const int hoff = h*8;

    // Pass 1: row maxima
    float m0 = -1e30f, m1 = -1e30f;
    for (int j = 0; j < 256; j++) {
        u64 s0 = 0ull, s1 = 0ull;
        #pragma unroll
        for (int d2 = 0; d2 < 8; d2++) {
            u64 k = Kp[j*32 + hoff + d2];
            s0 = ffma2(q0[d2], k, s0);
            s1 = ffma2(q1[d2], k, s1);
        }
        float a,b,c,d; up2(s0,a,b); up2(s1,c,d);
        m0 = fmaxf(m0, a+b); m1 = fmaxf(m1, c+d);
    }

    // Pass 2: exp, normalizer, AV accumulation
    float l0 = 0.0f, l1 = 0.0f;
    u64 o0[8], o1[8];
    #pragma unroll
    for (int d2 = 0; d2 < 8; d2++) { o0[d2] = 0ull; o1[d2] = 0ull; }

    for (int j = 0; j < 256; j++) {
        u64 s0 = 0ull, s1 = 0ull;
        #pragma unroll
        for (int d2 = 0; d2 < 8; d2++) {
            u64 k = Kp[j*32 + hoff + d2];
            s0 = ffma2(q0[d2], k, s0);
            s1 = ffma2(q1[d2], k, s1);
        }
        float a,b,c,d; up2(s0,a,b); up2(s1,c,d);
        float e0 = __expf(a + b - m0);
        float e1 = __expf(c + d - m1);
        l0 += e0; l1 += e1;
        u64 e00 = pk2(e0, e0), e11 = pk2(e1, e1);
        #pragma unroll
        for (int d2 = 0; d2 < 8; d2++) {
            u64 v = Vp[j*32 + hoff + d2];
            o0[d2] = ffma2(e00, v, o0[d2]);
            o1[d2] = ffma2(e11, v, o1[d2]);
        }
    }

    const float inv0 = 1.0f / l0, inv1 = 1.0f / l1;
    float* G0 = g_G + (size_t)(base + i0)*64 + h*16;
    float* G1 = g_G + (size_t)(base + i1)*64 + h*16;
    #pragma unroll
    for (int d2 = 0; d2 < 8; d2++) {
        float a,b; up2(o0[d2], a, b);
        G0[2*d2]   = a * inv0 * G0[2*d2];
        G0[2*d2+1] = b * inv0 * G0[2*d2+1];
        float c,d; up2(o1[d2], c, d);
        G1[2*d2]   = c * inv1 * G1[2*d2];
        G1[2*d2+1] = d * inv1 * G1[2*d2+1];
    }
}

// ---------------------------------------------------------------------------
// Kernel 3: output projection  y = (gated out) @ Wo.T + bo
// Block: 256 threads, 16 rows. Wo transposed in SMEM (pad 65).
// ---------------------------------------------------------------------------
__global__ void __launch_bounds__(256) k_out(
    const float* __restrict__ Wo, const float* __restrict__ bo,
    float* __restrict__ y)
{
    __shared__ float sW[64*65];        // sW[i*65 + o]
    __shared__ float s_in[16*64];

    const int tid  = threadIdx.x;
    const int row0 = blockIdx.x * 16;

    #pragma unroll
    for (int idx = tid; idx < 64*64; idx += 256) {
        int o = idx >> 6, i = idx & 63;
        sW[i*65 + o] = Wo[idx];
    }
    #pragma unroll
    for (int idx = tid; idx < 16*64; idx += 256) {
        s_in[idx] = g_G[(size_t)row0*64 + idx];
    }
    __syncthreads();

    const int c  = tid & 63;
    const int r0 = (tid >> 6) * 4;
    float acc[4] = {};
    #pragma unroll 4
    for (int i = 0; i < 64; i++) {
        float w = sW[i*65 + c];
        acc[0] += s_in[(r0+0)*64 + i] * w;
        acc[1] += s_in[(r0+1)*64 + i] * w;
        acc[2] += s_in[(r0+2)*64 + i] * w;
        acc[3] += s_in[(r0+3)*64 + i] * w;
    }
    const float bc = bo[c];
    #pragma unroll
    for (int r = 0; r < 4; r++) {
        y[(size_t)(row0 + r0 + r)*64 + c] = acc[r] + bc;
    }
}

// ---------------------------------------------------------------------------
extern "C" void kernel_launch(void* const* d_in, const int* in_sizes, int n_in,
                              void* d_out, int out_size)
{
    (void)in_sizes; (void)n_in; (void)out_size;
    const float* z  = (const float*)d_in[0];
    const float* ls = (const float*)d_in[1];
    const float* lb = (const float*)d_in[2];
    const float* Wq = (const float*)d_in[3];
    const float* Wk = (const float*)d_in[4];
    const float* Wv = (const float*)d_in[5];
    const float* Wg = (const float*)d_in[6];
    const float* bg = (const float*)d_in[7];
    const float* Wo = (const float*)d_in[8];
    const float* bo = (const float*)d_in[9];
    float* y = (float*)d_out;

    // Idempotent; harness's first (non-captured) correctness call latches these.
    (void)cudaFuncSetAttribute(k_ln_proj, cudaFuncAttributeMaxDynamicSharedMemorySize, K1_SMEM);
    (void)cudaFuncSetAttribute(k_attn,    cudaFuncAttributeMaxDynamicSharedMemorySize, K2_SMEM);

    k_ln_proj<<<NROWS/K1_ROWS, 256, K1_SMEM>>>(z, ls, lb, Wq, Wk, Wv, Wg, bg);
    k_attn<<<BATCH*LEN, 512, K2_SMEM>>>();
    k_out<<<NROWS/16, 256>>>(Wo, bo, y);
}

// round 2
// speedup vs baseline: 1.5207x; 1.5207x over previous
#include <cuda_runtime.h>
#include <cuda_bf16.h>

// Problem constants
#define BATCH 2
#define LEN   256
#define DMODEL 64
#define NROWS (BATCH*LEN*LEN)          // 131072

// Scratch (allocation-free rule: __device__ globals)
__device__ float g_Q[NROWS*DMODEL];
__device__ float g_K[NROWS*DMODEL];
__device__ float g_V[NROWS*DMODEL];
__device__ float g_G[NROWS*DMODEL];    // sigmoid gate

typedef unsigned long long u64;

__device__ __forceinline__ u64 pk2(float lo, float hi) {
    u64 r; asm("mov.b64 %0, {%1,%2};" : "=l"(r) : "f"(lo), "f"(hi)); return r;
}
__device__ __forceinline__ void up2(u64 v, float& lo, float& hi) {
    asm("mov.b64 {%0,%1}, %2;" : "=f"(lo), "=f"(hi) : "l"(v));
}
__device__ __forceinline__ u64 ffma2(u64 a, u64 b, u64 c) {
    u64 d; asm("fma.rn.f32x2 %0, %1, %2, %3;" : "=l"(d) : "l"(a), "l"(b), "l"(c)); return d;
}
__device__ __forceinline__ u64 fmul2(u64 a, u64 b) {
    u64 d; asm("mul.rn.f32x2 %0, %1, %2;" : "=l"(d) : "l"(a), "l"(b)); return d;
}
__device__ __forceinline__ float ex2(float x) {
    float r; asm("ex2.approx.f32 %0, %1;" : "=f"(r) : "f"(x)); return r;
}

// ---------------------------------------------------------------------------
// Kernel 1: LayerNorm + Q/K/V/Gate projections (FFMA2, row-pair packed).
// Block 256 threads / 32 rows. Weights natural [o][i] pad-68 (conflict-free
// float4 reads). zn stored row-pair interleaved: s_zp[pair][i][parity].
// Thread: channel c=tid&63, row-pair group pg=tid>>6 -> pairs 4pg..4pg+3.
// ---------------------------------------------------------------------------
#define K1_ROWS 32
#define K1_WS   68
#define K1_WMAT (64*K1_WS)                       // 4352 floats per matrix
#define K1_SMEM ((4*K1_WMAT + 16*128)*4)         // 77824 bytes

__global__ void __launch_bounds__(256) k_ln_proj(
    const float* __restrict__ z, const float* __restrict__ ln_scale,
    const float* __restrict__ ln_bias,
    const float* __restrict__ Wq, const float* __restrict__ Wk,
    const float* __restrict__ Wv, const float* __restrict__ Wg,
    const float* __restrict__ bg)
{
    extern __shared__ float sm1[];
    float* sW   = sm1;                   // [4][64][68]
    float* s_zp = sm1 + 4*K1_WMAT;       // [16 pairs][64 i][2 parity]

    const int tid  = threadIdx.x;
    const int row0 = blockIdx.x * K1_ROWS;

    // Stage weights (natural layout, padded rows)
    const float* Ws[4] = {Wq, Wk, Wv, Wg};
    #pragma unroll
    for (int m = 0; m < 4; m++) {
        const float* W = Ws[m];
        #pragma unroll
        for (int idx = tid; idx < 64*64; idx += 256) {
            int o = idx >> 6, i = idx & 63;
            sW[m*K1_WMAT + o*K1_WS + i] = W[idx];
        }
    }

    // LayerNorm: warp w -> rows 4w..4w+3; write pair-interleaved
    {
        const int w = tid >> 5, lane = tid & 31;
        #pragma unroll
        for (int rr = 0; rr < 4; rr++) {
            const int r = 4*w + rr;
            const float* zr = z + (size_t)(row0 + r) * 64;
            float a = zr[lane], b = zr[lane + 32];
            float s = a + b, ss = a*a + b*b;
            #pragma unroll
            for (int off = 16; off; off >>= 1) {
                s  += __shfl_xor_sync(0xffffffffu, s,  off);
                ss += __shfl_xor_sync(0xffffffffu, ss, off);
            }
            float mu  = s * (1.0f/64.0f);
            float var = ss * (1.0f/64.0f) - mu*mu;
            float rs  = rsqrtf(var + 1e-5f);
            float v0 = (a - mu) * rs * ln_scale[lane]      + ln_bias[lane];
            float v1 = (b - mu) * rs * ln_scale[lane + 32] + ln_bias[lane + 32];
            s_zp[(r>>1)*128 + lane*2      + (r&1)] = v0;
            s_zp[(r>>1)*128 + (lane+32)*2 + (r&1)] = v1;
        }
    }
    __syncthreads();

    const int c  = tid & 63;
    const int pg = tid >> 6;                      // pairs 4pg..4pg+3, rows 8pg..8pg+7
    u64 acc[4][4];
    #pragma unroll
    for (int m = 0; m < 4; m++)
        #pragma unroll
        for (int p = 0; p < 4; p++) acc[m][p] = 0ull;

    const float* wbase = sW + c*K1_WS;
    const float* zbase = s_zp + pg*4*128;

    #pragma unroll 4
    for (int i4 = 0; i4 < 16; i4++) {
        float4 w4[4];
        #pragma unroll
        for (int m = 0; m < 4; m++)
            w4[m] = *(const float4*)(wbase + m*K1_WMAT + i4*4);
        u64 zp[4][4];
        #pragma unroll
        for (int p = 0; p < 4; p++) {
            ulonglong2 a = *(const ulonglong2*)(zbase + p*128 + i4*8);
            ulonglong2 b = *(const ulonglong2*)(zbase + p*128 + i4*8 + 4);
            zp[p][0] = a.x; zp[p][1] = a.y; zp[p][2] = b.x; zp[p][3] = b.y;
        }
        #pragma unroll
        for (int m = 0; m < 4; m++) {
            float wv[4] = {w4[m].x, w4[m].y, w4[m].z, w4[m].w};
            #pragma unroll
            for (int ii = 0; ii < 4; ii++) {
                u64 wp = pk2(wv[ii], wv[ii]);
                #pragma unroll
                for (int p = 0; p < 4; p++)
                    acc[m][p] = ffma2(zp[p][ii], wp, acc[m][p]);
            }
        }
    }

    const float bgc = bg[c];
    #pragma unroll
    for (int p = 0; p < 4; p++) {
        const int re = row0 + 8*pg + 2*p;        // even row of pair
        float a, b;
        up2(acc[0][p], a, b);
        g_Q[(size_t)re*64 + c] = a;  g_Q[(size_t)(re+1)*64 + c] = b;
        up2(acc[1][p], a, b);
        g_K[(size_t)re*64 + c] = a;  g_K[(size_t)(re+1)*64 + c] = b;
        up2(acc[2][p], a, b);
        g_V[(size_t)re*64 + c] = a;  g_V[(size_t)(re+1)*64 + c] = b;
        up2(acc[3][p], a, b);
        g_G[(size_t)re*64 + c]     = 1.0f / (1.0f + __expf(-(a + bgc)));
        g_G[(size_t)(re+1)*64 + c] = 1.0f / (1.0f + __expf(-(b + bgc)));
    }
}

// ---------------------------------------------------------------------------
// Kernel 2: online-softmax attention + gate + fused output projection.
// Block 256 threads per (b,l). head h = tid>>6, t = tid&63, rows 4t..4t+3.
// SMEM: sK[256x64] | sV[256x64] during attention; reused as
//       sOp (row-pair interleaved gated output) | sWo afterwards.
// ---------------------------------------------------------------------------
#define K2_SMEM (2*256*64*4)   // 131072 bytes

__global__ void __launch_bounds__(256) k_attn(
    const float* __restrict__ Wo, const float* __restrict__ bo,
    float* __restrict__ y)
{
    extern __shared__ float sm2[];
    float* sK = sm2;
    float* sV = sm2 + 16384;

    const int tid  = threadIdx.x;
    const int base = blockIdx.x * 256;           // (b*L + l)

    {
        const float4* K4 = (const float4*)(g_K + (size_t)base * 64);
        const float4* V4 = (const float4*)(g_V + (size_t)base * 64);
        float4* sK4 = (float4*)sK; float4* sV4 = (float4*)sV;
        #pragma unroll
        for (int idx = tid; idx < 4096; idx += 256) {
            sK4[idx] = K4[idx];
            sV4[idx] = V4[idx];
        }
    }
    __syncthreads();

    const int h  = tid >> 6;
    const int t  = tid & 63;
    const int r0 = t * 4;                        // rows r0..r0+3

    // Q rows, prescaled by 0.25 * log2(e) (softmax in exp2 domain)
    const float QS = 0.25f * 1.4426950408889634f;
    u64 q[4][8];
    #pragma unroll
    for (int r = 0; r < 4; r++) {
        const float4* Qr = (const float4*)(g_Q + (size_t)(base + r0 + r)*64 + h*16);
        #pragma unroll
        for (int m = 0; m < 4; m++) {
            float4 a = Qr[m];
            q[r][2*m]   = pk2(a.x*QS, a.y*QS);
            q[r][2*m+1] = pk2(a.z*QS, a.w*QS);
        }
    }

    const ulonglong2* Kp2 = (const ulonglong2*)sK;   // row j -> j*16, head -> +h*4
    const ulonglong2* Vp2 = (const ulonglong2*)sV;
    const int hoff = h*4;

    const float NINF = __int_as_float(0xff800000);
    float m_[4] = {NINF, NINF, NINF, NINF};
    float l_[4] = {0.f, 0.f, 0.f, 0.f};
    u64 o[4][8];
    #pragma unroll
    for (int r = 0; r < 4; r++)
        #pragma unroll
        for (int d = 0; d < 8; d++) o[r][d] = 0ull;

    for (int c8 = 0; c8 < 32; c8++) {
        float s[4][8];
        // scores for 8 keys
        #pragma unroll
        for (int jj = 0; jj < 8; jj++) {
            const ulonglong2* kr = Kp2 + (c8*8 + jj)*16 + hoff;
            ulonglong2 ka = kr[0], kb = kr[1], kc = kr[2], kd = kr[3];
            u64 kk[8] = {ka.x, ka.y, kb.x, kb.y, kc.x, kc.y, kd.x, kd.y};
            #pragma unroll
            for (int r = 0; r < 4; r++) {
                u64 a2 = 0ull;
                #pragma unroll
                for (int d = 0; d < 8; d++) a2 = ffma2(q[r][d], kk[d], a2);
                float a, b; up2(a2, a, b);
                s[r][jj] = a + b;
            }
        }
        // online softmax update
        #pragma unroll
        for (int r = 0; r < 4; r++) {
            float mc = s[r][0];
            #pragma unroll
            for (int jj = 1; jj < 8; jj++) mc = fmaxf(mc, s[r][jj]);
            float mn = fmaxf(m_[r], mc);
            float f  = ex2(m_[r] - mn);
            m_[r] = mn;
            float ls = 0.f;
            #pragma unroll
            for (int jj = 0; jj < 8; jj++) {
                s[r][jj] = ex2(s[r][jj] - mn);
                ls += s[r][jj];
            }
            l_[r] = l_[r]*f + ls;
            u64 fp = pk2(f, f);
            #pragma unroll
            for (int d = 0; d < 8; d++) o[r][d] = fmul2(o[r][d], fp);
        }
        // accumulate V
        #pragma unroll
        for (int jj = 0; jj < 8; jj++) {
            const ulonglong2* vr = Vp2 + (c8*8 + jj)*16 + hoff;
            ulonglong2 va = vr[0], vb = vr[1], vc = vr[2], vd = vr[3];
            u64 vv[8] = {va.x, va.y, vb.x, vb.y, vc.x, vc.y, vd.x, vd.y};
            #pragma unroll
            for (int r = 0; r < 4; r++) {
                u64 ep = pk2(s[r][jj], s[r][jj]);
                #pragma unroll
                for (int d = 0; d < 8; d++) o[r][d] = ffma2(ep, vv[d], o[r][d]);
            }
        }
    }

    __syncthreads();   // everyone done reading sK/sV

    // normalize + gate, store row-pair interleaved into sOp (reuses sK space)
    float* sOp = sm2;                 // [128 pairs][64 ch][2 parity]
    float* sWo = sm2 + 16384;         // [64][68] + bo not staged (read global)
    u64*   sOpu = (u64*)sOp;

    #pragma unroll
    for (int pp = 0; pp < 2; pp++) {
        const int ra = 2*pp, rb = 2*pp + 1;
        const int p  = 2*t + pp;                 // pair index (rows r0+ra, r0+rb)
        const float inva = 1.0f / l_[ra];
        const float invb = 1.0f / l_[rb];
        const float* Ga = g_G + (size_t)(base + r0 + ra)*64 + h*16;
        const float* Gb = g_G + (size_t)(base + r0 + rb)*64 + h*16;
        #pragma unroll
        for (int d = 0; d < 8; d++) {
            float a0, a1; up2(o[ra][d], a0, a1);
            float b0, b1; up2(o[rb][d], b0, b1);
            a0 = a0 * inva * Ga[2*d];   a1 = a1 * inva * Ga[2*d+1];
            b0 = b0 * invb * Gb[2*d];   b1 = b1 * invb * Gb[2*d+1];
            const int ch = h*16 + 2*d;
            sOpu[p*64 + ch]     = pk2(a0, b0);
            sOpu[p*64 + ch + 1] = pk2(a1, b1);
        }
    }
    // stage Wo
    #pragma unroll
    for (int idx = tid; idx < 64*64; idx += 256) {
        int oc = idx >> 6, i = idx & 63;
        sWo[oc*K1_WS + i] = Wo[idx];
    }
    __syncthreads();

    // output projection: thread (c = tid&63, g = tid>>6) -> pairs g*32..g*32+31
    const int c = tid & 63;
    const int g = tid >> 6;
    u64 acc[32];
    #pragma unroll
    for (int pp = 0; pp < 32; pp++) acc[pp] = 0ull;

    const float* wbase = sWo + c*K1_WS;
    const u64*   zbase = sOpu + (size_t)g*32*64;

    #pragma unroll 2
    for (int i4 = 0; i4 < 16; i4++) {
        float4 w4 = *(const float4*)(wbase + i4*4);
        float wv[4] = {w4.x, w4.y, w4.z, w4.w};
        u64 wp[4];
        #pragma unroll
        for (int ii = 0; ii < 4; ii++) wp[ii] = pk2(wv[ii], wv[ii]);
        #pragma unroll
        for (int pp = 0; pp < 32; pp++) {
            ulonglong2 za = *(const ulonglong2*)(zbase + pp*64 + i4*4);
            ulonglong2 zb = *(const ulonglong2*)(zbase + pp*64 + i4*4 + 2);
            acc[pp] = ffma2(za.x, wp[0], acc[pp]);
            acc[pp] = ffma2(za.y, wp[1], acc[pp]);
            acc[pp] = ffma2(zb.x, wp[2], acc[pp]);
            acc[pp] = ffma2(zb.y, wp[3], acc[pp]);
        }
    }

    const float bc = bo[c];
    #pragma unroll
    for (int pp = 0; pp < 32; pp++) {
        const int pr = g*32 + pp;
        float a, b; up2(acc[pp], a, b);
        y[(size_t)(base + 2*pr)*64 + c]     = a + bc;
        y[(size_t)(base + 2*pr + 1)*64 + c] = b + bc;
    }
}

// ---------------------------------------------------------------------------
extern "C" void kernel_launch(void* const* d_in, const int* in_sizes, int n_in,
                              void* d_out, int out_size)
{
    (void)in_sizes; (void)n_in; (void)out_size;
    const float* z  = (const float*)d_in[0];
    const float* ls = (const float*)d_in[1];
    const float* lb = (const float*)d_in[2];
    const float* Wq = (const float*)d_in[3];
    const float* Wk = (const float*)d_in[4];
    const float* Wv = (const float*)d_in[5];
    const float* Wg = (const float*)d_in[6];
    const float* bg = (const float*)d_in[7];
    const float* Wo = (const float*)d_in[8];
    const float* bo = (const float*)d_in[9];
    float* y = (float*)d_out;

    (void)cudaFuncSetAttribute(k_ln_proj, cudaFuncAttributeMaxDynamicSharedMemorySize, K1_SMEM);
    (void)cudaFuncSetAttribute(k_attn,    cudaFuncAttributeMaxDynamicSharedMemorySize, K2_SMEM);

    k_ln_proj<<<NROWS/K1_ROWS, 256, K1_SMEM>>>(z, ls, lb, Wq, Wk, Wv, Wg, bg);
    k_attn<<<BATCH*LEN, 256, K2_SMEM>>>(Wo, bo, y);
}